// round 4
// baseline (speedup 1.0000x reference)
#include <cuda_runtime.h>
#include <cuda_bf16.h>

// Problem constants
#define NN      8192
#define GEV     32
#define PER     256      // nodes per event
#define KK      15
#define FIN     4
#define FOUT    4
#define LATD    64
#define HIDD    128

#define H_ELEMS   (NN * LATD)          // 524288
#define XE_ELEMS  (NN * FOUT)          // 32768
#define NKE       (NN * KK)            // 122880
#define XE_OFF    (H_ELEMS)
#define EI_OFF    (H_ELEMS + XE_ELEMS) // 557056

#define FULLMASK 0xffffffffu

// Device scratch (no allocations allowed)
__device__ float g_h0[NN * LATD];
__device__ float g_h1[NN * LATD];
__device__ int   g_nbr[NN * KK];

// ---------------------------------------------------------------------------
// Kernel 1: fused space_emb FFN + event-local kNN.
// One CTA per event, 1024 threads. 4 threads per row compute the FFN
// (16 output cols each); q==0 threads deposit cols 0..2 into smem position
// arrays; then 256 threads run the kNN scan (1 thread per query).
// ---------------------------------------------------------------------------
__global__ void __launch_bounds__(1024, 1)
k_space_knn(const float* __restrict__ x,
            const float* __restrict__ W1, const float* __restrict__ b1,
            const float* __restrict__ W2, const float* __restrict__ b2,
            float* __restrict__ hout,
            int* __restrict__ nbr,
            float* __restrict__ out_ei) {
    __shared__ float sW1[FIN * LATD];
    __shared__ float sb1[LATD];
    __shared__ float sW2[LATD * LATD];
    __shared__ float sb2[LATD];
    __shared__ float px[PER], py[PER], pz[PER];

    int tid  = threadIdx.x;
    int base = blockIdx.x * PER;

    if (tid < FIN * LATD) sW1[tid] = W1[tid];
    if (tid >= FIN * LATD && tid < FIN * LATD + LATD) sb1[tid - FIN * LATD] = b1[tid - FIN * LATD];
    if (tid >= 512 && tid < 512 + LATD) sb2[tid - 512] = b2[tid - 512];
    ((float4*)sW2)[tid] = ((const float4*)W2)[tid];   // 4096 floats = 1024 float4
    __syncthreads();

    int lrow = tid >> 2;               // 0..255
    int q    = tid & 3;
    int c0   = q * 16;
    int row  = base + lrow;

    float xi0 = x[row * FIN + 0];
    float xi1 = x[row * FIN + 1];
    float xi2 = x[row * FIN + 2];
    float xi3 = x[row * FIN + 3];

    float acc[16];
#pragma unroll
    for (int c = 0; c < 16; ++c) acc[c] = sb2[c0 + c];

#pragma unroll 4
    for (int j = 0; j < LATD; ++j) {
        float tj = sb1[j]
                 + xi0 * sW1[0 * LATD + j]
                 + xi1 * sW1[1 * LATD + j]
                 + xi2 * sW1[2 * LATD + j]
                 + xi3 * sW1[3 * LATD + j];
        tj = (tj > 0.0f) ? tj : 0.01f * tj;
        const float* w2r = &sW2[j * LATD + c0];
#pragma unroll
        for (int c = 0; c < 16; ++c) acc[c] += tj * w2r[c];
    }
    float* o = &hout[row * LATD + c0];
#pragma unroll
    for (int c = 0; c < 16; ++c) o[c] = acc[c];
    if (q == 0) { px[lrow] = acc[0]; py[lrow] = acc[1]; pz[lrow] = acc[2]; }
    __syncthreads();

    // ---- kNN: 1 thread per query ------------------------------------------
    if (tid < PER) {
        int lq  = tid;
        int gid = base + lq;

        float bd[KK];
        int   bi[KK];
#pragma unroll
        for (int s = 0; s < KK; ++s) { bd[s] = 3.0e38f; bi[s] = 0; }

        float xq = px[lq], yq = py[lq], zq = pz[lq];

        for (int j = 0; j < PER; ++j) {
            float dx = __fadd_rn(xq, -px[j]);
            float dy = __fadd_rn(yq, -py[j]);
            float dz = __fadd_rn(zq, -pz[j]);
            float d  = __fadd_rn(__fadd_rn(__fmul_rn(dx, dx), __fmul_rn(dy, dy)),
                                 __fmul_rn(dz, dz));
            if (j == lq) d = 3.3e38f;            // exclude self
            if (d < bd[KK - 1]) {
#pragma unroll
                for (int p = KK - 1; p >= 0; --p) {
                    bool shift = (p > 0) && (d < bd[p - 1]);
                    bool place = !shift && (d < bd[p]);
                    if (shift)      { bd[p] = bd[p - 1]; bi[p] = bi[p - 1]; }
                    else if (place) { bd[p] = d;         bi[p] = j;         }
                }
            }
        }

        float fgid = (float)gid;
#pragma unroll
        for (int s = 0; s < KK; ++s) {
            int gj = base + bi[s];
            int e  = gid * KK + s;
            nbr[e] = gj;
            out_ei[e]       = (float)gj;
            out_ei[NKE + e] = fgid;
        }
    }
}

// ---------------------------------------------------------------------------
// Kernel 2: GIN layer, warp-autonomous register-blocked, vectorized LDS.
// 256 threads, 8 warps, 4 rows per warp, grid 256 (32 rows/block).
// Weights stored PERMUTED in smem so each lane's strided weights are one
// LDS.128 (Wa) / LDS.64 (Wb, W1o). m and t broadcast via shfl.
// FUSE_OE: gin2 computes x_emb in an epilogue from the register-resident h.
// ---------------------------------------------------------------------------
template <bool FUSE_OE>
__global__ void __launch_bounds__(256, 2)
k_gin(const float* __restrict__ h_in,
      float* __restrict__ h_out,
      const int* __restrict__ nbr,
      const float* __restrict__ Wa, const float* __restrict__ ba,
      const float* __restrict__ Wb, const float* __restrict__ bb,
      const float* __restrict__ W1o, const float* __restrict__ b1o,
      const float* __restrict__ W2o, const float* __restrict__ b2o,
      float* __restrict__ xe) {
    extern __shared__ float sm[];
    float* sWaP = sm;                          // 64*128 permuted
    float* sWbP = sWaP + LATD * HIDD;          // 128*64 permuted
    float* sba  = sWbP + HIDD * LATD;          // 128
    float* sbb  = sba + HIDD;                  // 64
    float* sW1oP = sbb + LATD;                 // 64*64 permuted (FUSE_OE)
    float* sb1o  = sW1oP + LATD * LATD;        // 64
    float* sW2o  = sb1o + LATD;                // 64*4
    float* sb2o  = sW2o + LATD * FOUT;         // 4

    int tid = threadIdx.x;
    // permuted weight staging
    {
        const float4* Wa4 = (const float4*)Wa;
        const float4* Wb4 = (const float4*)Wb;
#pragma unroll
        for (int it = 0; it < (LATD * HIDD) / 4 / 256; ++it) {
            int f4 = tid + it * 256;
            // Wa: row k (0..63), 32 float4 per row
            {
                int k  = f4 >> 5;
                int c4 = f4 & 31;
                float4 v = Wa4[f4];
                int qq = c4 >> 3;
                int l0 = (4 * c4) & 31;
                int d  = k * HIDD + l0 * 4 + qq;
                sWaP[d]      = v.x;
                sWaP[d + 4]  = v.y;
                sWaP[d + 8]  = v.z;
                sWaP[d + 12] = v.w;
            }
            // Wb: row j (0..127), 16 float4 per row
            {
                int j  = f4 >> 4;
                int c4 = f4 & 15;
                float4 v = Wb4[f4];
                int hh = c4 >> 3;
                int l0 = (4 * c4) & 31;
                int d  = j * LATD + l0 * 2 + hh;
                sWbP[d]     = v.x;
                sWbP[d + 2] = v.y;
                sWbP[d + 4] = v.z;
                sWbP[d + 6] = v.w;
            }
        }
        if (tid < HIDD) sba[tid] = ba[tid];
        if (tid < LATD) sbb[tid] = bb[tid];
        if (FUSE_OE) {
            const float4* W1o4 = (const float4*)W1o;
#pragma unroll
            for (int it = 0; it < (LATD * LATD) / 4 / 256; ++it) {
                int f4 = tid + it * 256;
                int c  = f4 >> 4;
                int c4 = f4 & 15;
                float4 v = W1o4[f4];
                int hh = c4 >> 3;
                int l0 = (4 * c4) & 31;
                int d  = c * LATD + l0 * 2 + hh;
                sW1oP[d]     = v.x;
                sW1oP[d + 2] = v.y;
                sW1oP[d + 4] = v.z;
                sW1oP[d + 6] = v.w;
            }
            if (tid < LATD) sb1o[tid] = b1o[tid];
            if (tid < LATD * FOUT) sW2o[tid] = W2o[tid];
            if (tid < FOUT) sb2o[tid] = b2o[tid];
        }
    }
    __syncthreads();

    int warp = tid >> 5;
    int lane = tid & 31;
    int base = blockIdx.x * 32 + warp * 4;    // first of this warp's 4 rows

    // ---- Phase A: gather. lane owns columns (2*lane, 2*lane+1) of m -------
    float mlo[4], mhi[4];
    const float2* h2 = (const float2*)h_in;
#pragma unroll
    for (int r = 0; r < 4; ++r) {
        int i = base + r;
        const int* nb = &nbr[i * KK];
        float2 a = h2[i * 32 + lane];
        float ax = a.x, ay = a.y;
#pragma unroll
        for (int s = 0; s < KK; ++s) {
            float2 v = h2[nb[s] * 32 + lane];
            ax += v.x; ay += v.y;
        }
        mlo[r] = ax; mhi[r] = ay;
    }

    // ---- Phase B: t = relu(m @ Wa + ba). lane owns j = lane + 32q --------
    float t0[4], t1[4], t2[4], t3[4];
    {
        float bv0 = sba[lane], bv1 = sba[lane + 32];
        float bv2 = sba[lane + 64], bv3 = sba[lane + 96];
#pragma unroll
        for (int r = 0; r < 4; ++r) { t0[r] = bv0; t1[r] = bv1; t2[r] = bv2; t3[r] = bv3; }
    }
#pragma unroll 4
    for (int k2 = 0; k2 < 32; ++k2) {
#pragma unroll
        for (int kk = 0; kk < 2; ++kk) {
            int k = 2 * k2 + kk;
            float4 w = *(const float4*)&sWaP[k * HIDD + lane * 4];
#pragma unroll
            for (int r = 0; r < 4; ++r) {
                float mk = __shfl_sync(FULLMASK, kk ? mhi[r] : mlo[r], k2);
                t0[r] += mk * w.x;
                t1[r] += mk * w.y;
                t2[r] += mk * w.z;
                t3[r] += mk * w.w;
            }
        }
    }
#pragma unroll
    for (int r = 0; r < 4; ++r) {
        t0[r] = fmaxf(t0[r], 0.0f);
        t1[r] = fmaxf(t1[r], 0.0f);
        t2[r] = fmaxf(t2[r], 0.0f);
        t3[r] = fmaxf(t3[r], 0.0f);
    }

    // ---- Phase C: out = h + t @ Wb + bb. lane owns c = lane, lane+32 -----
    float o0[4], o1[4];
    {
        float bv0 = sbb[lane], bv1 = sbb[lane + 32];
#pragma unroll
        for (int r = 0; r < 4; ++r) { o0[r] = bv0; o1[r] = bv1; }
    }
#pragma unroll
    for (int q = 0; q < 4; ++q) {
#pragma unroll 4
        for (int jj = 0; jj < 32; ++jj) {
            int j = q * 32 + jj;
            float2 w = *(const float2*)&sWbP[j * LATD + lane * 2];
#pragma unroll
            for (int r = 0; r < 4; ++r) {
                float tv = (q == 0) ? t0[r] : (q == 1) ? t1[r] : (q == 2) ? t2[r] : t3[r];
                float tj = __shfl_sync(FULLMASK, tv, jj);
                o0[r] += tj * w.x;
                o1[r] += tj * w.y;
            }
        }
    }

    // final h for this warp's rows (lane owns columns lane, lane+32)
    float hf0[4], hf1[4];
#pragma unroll
    for (int r = 0; r < 4; ++r) {
        int i = base + r;
        hf0[r] = h_in[i * LATD + lane]      + o0[r];
        hf1[r] = h_in[i * LATD + lane + 32] + o1[r];
        h_out[i * LATD + lane]      = hf0[r];
        h_out[i * LATD + lane + 32] = hf1[r];
    }

    if (FUSE_OE) {
        // ---- Epilogue: x_emb = leaky(h@W1o+b1o)@W2o+b2o --------------------
        float u0[4], u1[4];
        {
            float bv0 = sb1o[lane], bv1 = sb1o[lane + 32];
#pragma unroll
            for (int r = 0; r < 4; ++r) { u0[r] = bv0; u1[r] = bv1; }
        }
#pragma unroll 4
        for (int c = 0; c < LATD; ++c) {
            float2 w = *(const float2*)&sW1oP[c * LATD + lane * 2];
#pragma unroll
            for (int r = 0; r < 4; ++r) {
                float hc = (c < 32) ? __shfl_sync(FULLMASK, hf0[r], c)
                                    : __shfl_sync(FULLMASK, hf1[r], c - 32);
                u0[r] += hc * w.x;
                u1[r] += hc * w.y;
            }
        }
        float wA0 = sW2o[lane * FOUT + 0], wA1 = sW2o[lane * FOUT + 1];
        float wA2 = sW2o[lane * FOUT + 2], wA3 = sW2o[lane * FOUT + 3];
        float wB0 = sW2o[(lane + 32) * FOUT + 0], wB1 = sW2o[(lane + 32) * FOUT + 1];
        float wB2 = sW2o[(lane + 32) * FOUT + 2], wB3 = sW2o[(lane + 32) * FOUT + 3];
#pragma unroll
        for (int r = 0; r < 4; ++r) {
            float a = u0[r]; a = (a > 0.0f) ? a : 0.01f * a;
            float b = u1[r]; b = (b > 0.0f) ? b : 0.01f * b;
            float p0 = a * wA0 + b * wB0;
            float p1 = a * wA1 + b * wB1;
            float p2 = a * wA2 + b * wB2;
            float p3 = a * wA3 + b * wB3;
#pragma unroll
            for (int off = 16; off > 0; off >>= 1) {
                p0 += __shfl_xor_sync(FULLMASK, p0, off);
                p1 += __shfl_xor_sync(FULLMASK, p1, off);
                p2 += __shfl_xor_sync(FULLMASK, p2, off);
                p3 += __shfl_xor_sync(FULLMASK, p3, off);
            }
            if (lane == 0) {
                int i = base + r;
                xe[i * FOUT + 0] = p0 + sb2o[0];
                xe[i * FOUT + 1] = p1 + sb2o[1];
                xe[i * FOUT + 2] = p2 + sb2o[2];
                xe[i * FOUT + 3] = p3 + sb2o[3];
            }
        }
    }
}

// ---------------------------------------------------------------------------
extern "C" void kernel_launch(void* const* d_in, const int* in_sizes, int n_in,
                              void* d_out, int out_size) {
    const float* x     = (const float*)d_in[0];
    const float* W_se1 = (const float*)d_in[3];
    const float* b_se1 = (const float*)d_in[4];
    const float* W_se2 = (const float*)d_in[5];
    const float* b_se2 = (const float*)d_in[6];
    const float* W_g1a = (const float*)d_in[7];
    const float* b_g1a = (const float*)d_in[8];
    const float* W_g1b = (const float*)d_in[9];
    const float* b_g1b = (const float*)d_in[10];
    const float* W_g2a = (const float*)d_in[11];
    const float* b_g2a = (const float*)d_in[12];
    const float* W_g2b = (const float*)d_in[13];
    const float* b_g2b = (const float*)d_in[14];
    const float* W_oe1 = (const float*)d_in[15];
    const float* b_oe1 = (const float*)d_in[16];
    const float* W_oe2 = (const float*)d_in[17];
    const float* b_oe2 = (const float*)d_in[18];

    float* out    = (float*)d_out;
    float* out_h  = out;
    float* out_xe = out + XE_OFF;
    float* out_ei = out + EI_OFF;

    void *p_h0, *p_h1, *p_nbr;
    cudaGetSymbolAddress(&p_h0, g_h0);
    cudaGetSymbolAddress(&p_h1, g_h1);
    cudaGetSymbolAddress(&p_nbr, g_nbr);
    float* h0 = (float*)p_h0;
    float* h1 = (float*)p_h1;
    int*   nb = (int*)p_nbr;

    static const size_t gin_smem_base =
        (LATD * HIDD + HIDD * LATD + HIDD + LATD) * sizeof(float);
    static const size_t gin_smem_oe = gin_smem_base +
        (LATD * LATD + LATD + LATD * FOUT + FOUT) * sizeof(float);
    cudaFuncSetAttribute(k_gin<false>, cudaFuncAttributeMaxDynamicSharedMemorySize,
                         (int)gin_smem_base);
    cudaFuncSetAttribute(k_gin<true>, cudaFuncAttributeMaxDynamicSharedMemorySize,
                         (int)gin_smem_oe);

    // 1) fused space_emb + kNN -> h0, nbr, ei
    k_space_knn<<<GEV, 1024>>>(x, W_se1, b_se1, W_se2, b_se2, h0, nb, out_ei);
    // 2) GIN layer 1: h0 -> h1
    k_gin<false><<<NN / 32, 256, gin_smem_base>>>(h0, h1, nb,
        W_g1a, b_g1a, W_g1b, b_g1b, nullptr, nullptr, nullptr, nullptr, nullptr);
    // 3) GIN layer 2 + fused out_emb: h1 -> d_out (h), x_emb -> d_out
    k_gin<true><<<NN / 32, 256, gin_smem_oe>>>(h1, out_h, nb,
        W_g2a, b_g2a, W_g2b, b_g2b, W_oe1, b_oe1, W_oe2, b_oe2, out_xe);
}

// round 5
// speedup vs baseline: 1.7973x; 1.7973x over previous
#include <cuda_runtime.h>
#include <cuda_bf16.h>

// Problem constants
#define NN      8192
#define GEV     32
#define PER     256      // nodes per event
#define KK      15
#define FIN     4
#define FOUT    4
#define LATD    64
#define HIDD    128

#define H_ELEMS   (NN * LATD)          // 524288
#define XE_ELEMS  (NN * FOUT)          // 32768
#define NKE       (NN * KK)            // 122880
#define XE_OFF    (H_ELEMS)
#define EI_OFF    (H_ELEMS + XE_ELEMS) // 557056

#define FULLMASK 0xffffffffu

// Device scratch (no allocations allowed)
__device__ float g_h0[NN * LATD];
__device__ float g_h1[NN * LATD];
__device__ int   g_nbr[NN * KK];

// ---------------------------------------------------------------------------
// Kernel 1: space_emb FFN  h = leaky(x@W1+b1)@W2+b2
// 4 threads per row, each owns 16 output columns. grid 128 x 256.
// ---------------------------------------------------------------------------
__global__ void k_space_emb(const float* __restrict__ x,
                            const float* __restrict__ W1, const float* __restrict__ b1,
                            const float* __restrict__ W2, const float* __restrict__ b2,
                            float* __restrict__ hout) {
    __shared__ float sW1[FIN * LATD];
    __shared__ float sb1[LATD];
    __shared__ float sW2[LATD * LATD];
    __shared__ float sb2[LATD];
    int tid = threadIdx.x;
    for (int i = tid; i < FIN * LATD; i += blockDim.x) sW1[i] = W1[i];
    for (int i = tid; i < LATD; i += blockDim.x) { sb1[i] = b1[i]; sb2[i] = b2[i]; }
    {
        float4* sW24 = (float4*)sW2;
        const float4* W24 = (const float4*)W2;
#pragma unroll
        for (int i = 0; i < (LATD * LATD) / 4 / 256; ++i)
            sW24[tid + i * 256] = W24[tid + i * 256];
    }
    __syncthreads();

    int row = blockIdx.x * 64 + (tid >> 2);
    int q   = tid & 3;
    int c0  = q * 16;

    float xi0 = x[row * FIN + 0];
    float xi1 = x[row * FIN + 1];
    float xi2 = x[row * FIN + 2];
    float xi3 = x[row * FIN + 3];

    float acc[16];
#pragma unroll
    for (int c = 0; c < 16; ++c) acc[c] = sb2[c0 + c];

#pragma unroll 4
    for (int j = 0; j < LATD; ++j) {
        float tj = sb1[j]
                 + xi0 * sW1[0 * LATD + j]
                 + xi1 * sW1[1 * LATD + j]
                 + xi2 * sW1[2 * LATD + j]
                 + xi3 * sW1[3 * LATD + j];
        tj = (tj > 0.0f) ? tj : 0.01f * tj;
        const float* w2r = &sW2[j * LATD + c0];
#pragma unroll
        for (int c = 0; c < 16; ++c) acc[c] += tj * w2r[c];
    }
    float* o = &hout[row * LATD + c0];
#pragma unroll
    for (int c = 0; c < 16; ++c) o[c] = acc[c];
}

// ---------------------------------------------------------------------------
// Kernel 2: event-local kNN (k=15) on h[:, :3].
// 4 blocks per event, 64 queries per block, 128 threads: 2 threads per query
// (even/odd candidate strides), each keeps a sorted top-15, then a smem merge
// with (distance, index) lexicographic order — matches lax.top_k tie-breaking.
// ---------------------------------------------------------------------------
__global__ void k_knn(const float* __restrict__ h,
                      int* __restrict__ nbr,
                      float* __restrict__ out_ei) {
    __shared__ float px[PER], py[PER], pz[PER];
    __shared__ float md[128][KK];
    __shared__ int   mi[128][KK];

    int tid  = threadIdx.x;           // 0..127
    int ev   = blockIdx.x >> 2;
    int quad = blockIdx.x & 3;
    int base = ev * PER;

#pragma unroll
    for (int s = 0; s < 2; ++s) {
        int n = tid + s * 128;
        px[n] = h[(base + n) * LATD + 0];
        py[n] = h[(base + n) * LATD + 1];
        pz[n] = h[(base + n) * LATD + 2];
    }
    __syncthreads();

    int lq   = quad * 64 + (tid >> 1); // local query index in event
    int half = tid & 1;                // candidate parity

    float bd[KK];
    int   bi[KK];
#pragma unroll
    for (int s = 0; s < KK; ++s) { bd[s] = 3.0e38f; bi[s] = 0; }

    float xi = px[lq], yi = py[lq], zi = pz[lq];

    for (int j = half; j < PER; j += 2) {
        float dx = __fadd_rn(xi, -px[j]);
        float dy = __fadd_rn(yi, -py[j]);
        float dz = __fadd_rn(zi, -pz[j]);
        float d  = __fadd_rn(__fadd_rn(__fmul_rn(dx, dx), __fmul_rn(dy, dy)),
                             __fmul_rn(dz, dz));
        if (j == lq) d = 3.3e38f;            // exclude self
        if (d < bd[KK - 1]) {
#pragma unroll
            for (int p = KK - 1; p >= 0; --p) {
                bool shift = (p > 0) && (d < bd[p - 1]);
                bool place = !shift && (d < bd[p]);
                if (shift)      { bd[p] = bd[p - 1]; bi[p] = bi[p - 1]; }
                else if (place) { bd[p] = d;         bi[p] = j;         }
            }
        }
    }
#pragma unroll
    for (int s = 0; s < KK; ++s) { md[tid][s] = bd[s]; mi[tid][s] = bi[s]; }
    __syncthreads();

    // merge: thread t (<64) merges rows 2t (even j) and 2t+1 (odd j)
    if (tid < 64) {
        int q   = quad * 64 + tid;
        int gid = base + q;
        float fgid = (float)gid;
        int a = 0, b = 0;
        int ra = 2 * tid, rb = 2 * tid + 1;
#pragma unroll
        for (int s = 0; s < KK; ++s) {
            float da = md[ra][a], db = md[rb][b];
            int   ia = mi[ra][a], ib = mi[rb][b];
            bool takeA = (da < db) || (da == db && ia < ib);
            int  pick  = takeA ? ia : ib;
            if (takeA) ++a; else ++b;
            int gj = base + pick;
            int e  = gid * KK + s;
            nbr[e] = gj;
            out_ei[e]       = (float)gj;
            out_ei[NKE + e] = fgid;
        }
    }
}

// ---------------------------------------------------------------------------
// Kernel 3: GIN layer, warp-autonomous register-blocked, vectorized LDS.
// 256 threads, 8 warps, 4 rows per warp, grid 256 (32 rows/block).
// Weights stored PERMUTED in smem so each lane's strided weights are one
// LDS.128 (Wa) / LDS.64 (Wb, W1o). m and t broadcast via shfl.
// FUSE_OE: gin2 computes x_emb in an epilogue from the register-resident h.
// ---------------------------------------------------------------------------
template <bool FUSE_OE>
__global__ void __launch_bounds__(256, 2)
k_gin(const float* __restrict__ h_in,
      float* __restrict__ h_out,
      const int* __restrict__ nbr,
      const float* __restrict__ Wa, const float* __restrict__ ba,
      const float* __restrict__ Wb, const float* __restrict__ bb,
      const float* __restrict__ W1o, const float* __restrict__ b1o,
      const float* __restrict__ W2o, const float* __restrict__ b2o,
      float* __restrict__ xe) {
    extern __shared__ float sm[];
    float* sWaP = sm;                          // 64*128 permuted
    float* sWbP = sWaP + LATD * HIDD;          // 128*64 permuted
    float* sba  = sWbP + HIDD * LATD;          // 128
    float* sbb  = sba + HIDD;                  // 64
    float* sW1oP = sbb + LATD;                 // 64*64 permuted (FUSE_OE)
    float* sb1o  = sW1oP + LATD * LATD;        // 64
    float* sW2o  = sb1o + LATD;                // 64*4
    float* sb2o  = sW2o + LATD * FOUT;         // 4

    int tid = threadIdx.x;
    {
        const float4* Wa4 = (const float4*)Wa;
        const float4* Wb4 = (const float4*)Wb;
#pragma unroll
        for (int it = 0; it < (LATD * HIDD) / 4 / 256; ++it) {
            int f4 = tid + it * 256;
            // Wa: row k (0..63), 32 float4 per row
            {
                int k  = f4 >> 5;
                int c4 = f4 & 31;
                float4 v = Wa4[f4];
                int qq = c4 >> 3;
                int l0 = (4 * c4) & 31;
                int d  = k * HIDD + l0 * 4 + qq;
                sWaP[d]      = v.x;
                sWaP[d + 4]  = v.y;
                sWaP[d + 8]  = v.z;
                sWaP[d + 12] = v.w;
            }
            // Wb: row j (0..127), 16 float4 per row
            {
                int j  = f4 >> 4;
                int c4 = f4 & 15;
                float4 v = Wb4[f4];
                int hh = c4 >> 3;
                int l0 = (4 * c4) & 31;
                int d  = j * LATD + l0 * 2 + hh;
                sWbP[d]     = v.x;
                sWbP[d + 2] = v.y;
                sWbP[d + 4] = v.z;
                sWbP[d + 6] = v.w;
            }
        }
        if (tid < HIDD) sba[tid] = ba[tid];
        if (tid < LATD) sbb[tid] = bb[tid];
        if (FUSE_OE) {
            const float4* W1o4 = (const float4*)W1o;
#pragma unroll
            for (int it = 0; it < (LATD * LATD) / 4 / 256; ++it) {
                int f4 = tid + it * 256;
                int c  = f4 >> 4;
                int c4 = f4 & 15;
                float4 v = W1o4[f4];
                int hh = c4 >> 3;
                int l0 = (4 * c4) & 31;
                int d  = c * LATD + l0 * 2 + hh;
                sW1oP[d]     = v.x;
                sW1oP[d + 2] = v.y;
                sW1oP[d + 4] = v.z;
                sW1oP[d + 6] = v.w;
            }
            if (tid < LATD) sb1o[tid] = b1o[tid];
            if (tid < LATD * FOUT) sW2o[tid] = W2o[tid];
            if (tid < FOUT) sb2o[tid] = b2o[tid];
        }
    }
    __syncthreads();

    int warp = tid >> 5;
    int lane = tid & 31;
    int base = blockIdx.x * 32 + warp * 4;    // first of this warp's 4 rows

    // ---- Phase A: gather. lane owns columns (2*lane, 2*lane+1) of m -------
    float mlo[4], mhi[4];
    const float2* h2 = (const float2*)h_in;
#pragma unroll
    for (int r = 0; r < 4; ++r) {
        int i = base + r;
        const int* nb = &nbr[i * KK];
        float2 a = h2[i * 32 + lane];
        float ax = a.x, ay = a.y;
#pragma unroll
        for (int s = 0; s < KK; ++s) {
            float2 v = h2[nb[s] * 32 + lane];
            ax += v.x; ay += v.y;
        }
        mlo[r] = ax; mhi[r] = ay;
    }

    // ---- Phase B: t = relu(m @ Wa + ba). lane owns j = lane + 32q --------
    float t0[4], t1[4], t2[4], t3[4];
    {
        float bv0 = sba[lane], bv1 = sba[lane + 32];
        float bv2 = sba[lane + 64], bv3 = sba[lane + 96];
#pragma unroll
        for (int r = 0; r < 4; ++r) { t0[r] = bv0; t1[r] = bv1; t2[r] = bv2; t3[r] = bv3; }
    }
#pragma unroll 4
    for (int k2 = 0; k2 < 32; ++k2) {
#pragma unroll
        for (int kk = 0; kk < 2; ++kk) {
            int k = 2 * k2 + kk;
            float4 w = *(const float4*)&sWaP[k * HIDD + lane * 4];
#pragma unroll
            for (int r = 0; r < 4; ++r) {
                float mk = __shfl_sync(FULLMASK, kk ? mhi[r] : mlo[r], k2);
                t0[r] += mk * w.x;
                t1[r] += mk * w.y;
                t2[r] += mk * w.z;
                t3[r] += mk * w.w;
            }
        }
    }
#pragma unroll
    for (int r = 0; r < 4; ++r) {
        t0[r] = fmaxf(t0[r], 0.0f);
        t1[r] = fmaxf(t1[r], 0.0f);
        t2[r] = fmaxf(t2[r], 0.0f);
        t3[r] = fmaxf(t3[r], 0.0f);
    }

    // ---- Phase C: out = h + t @ Wb + bb. lane owns c = lane, lane+32 -----
    float o0[4], o1[4];
    {
        float bv0 = sbb[lane], bv1 = sbb[lane + 32];
#pragma unroll
        for (int r = 0; r < 4; ++r) { o0[r] = bv0; o1[r] = bv1; }
    }
#pragma unroll
    for (int q = 0; q < 4; ++q) {
#pragma unroll 4
        for (int jj = 0; jj < 32; ++jj) {
            int j = q * 32 + jj;
            float2 w = *(const float2*)&sWbP[j * LATD + lane * 2];
#pragma unroll
            for (int r = 0; r < 4; ++r) {
                float tv = (q == 0) ? t0[r] : (q == 1) ? t1[r] : (q == 2) ? t2[r] : t3[r];
                float tj = __shfl_sync(FULLMASK, tv, jj);
                o0[r] += tj * w.x;
                o1[r] += tj * w.y;
            }
        }
    }

    // final h for this warp's rows (lane owns columns lane, lane+32)
    float hf0[4], hf1[4];
#pragma unroll
    for (int r = 0; r < 4; ++r) {
        int i = base + r;
        hf0[r] = h_in[i * LATD + lane]      + o0[r];
        hf1[r] = h_in[i * LATD + lane + 32] + o1[r];
        h_out[i * LATD + lane]      = hf0[r];
        h_out[i * LATD + lane + 32] = hf1[r];
    }

    if (FUSE_OE) {
        // ---- Epilogue: x_emb = leaky(h@W1o+b1o)@W2o+b2o --------------------
        float u0[4], u1[4];
        {
            float bv0 = sb1o[lane], bv1 = sb1o[lane + 32];
#pragma unroll
            for (int r = 0; r < 4; ++r) { u0[r] = bv0; u1[r] = bv1; }
        }
#pragma unroll 4
        for (int c = 0; c < LATD; ++c) {
            float2 w = *(const float2*)&sW1oP[c * LATD + lane * 2];
#pragma unroll
            for (int r = 0; r < 4; ++r) {
                float hc = (c < 32) ? __shfl_sync(FULLMASK, hf0[r], c)
                                    : __shfl_sync(FULLMASK, hf1[r], c - 32);
                u0[r] += hc * w.x;
                u1[r] += hc * w.y;
            }
        }
        float wA0 = sW2o[lane * FOUT + 0], wA1 = sW2o[lane * FOUT + 1];
        float wA2 = sW2o[lane * FOUT + 2], wA3 = sW2o[lane * FOUT + 3];
        float wB0 = sW2o[(lane + 32) * FOUT + 0], wB1 = sW2o[(lane + 32) * FOUT + 1];
        float wB2 = sW2o[(lane + 32) * FOUT + 2], wB3 = sW2o[(lane + 32) * FOUT + 3];
#pragma unroll
        for (int r = 0; r < 4; ++r) {
            float a = u0[r]; a = (a > 0.0f) ? a : 0.01f * a;
            float b = u1[r]; b = (b > 0.0f) ? b : 0.01f * b;
            float p0 = a * wA0 + b * wB0;
            float p1 = a * wA1 + b * wB1;
            float p2 = a * wA2 + b * wB2;
            float p3 = a * wA3 + b * wB3;
#pragma unroll
            for (int off = 16; off > 0; off >>= 1) {
                p0 += __shfl_xor_sync(FULLMASK, p0, off);
                p1 += __shfl_xor_sync(FULLMASK, p1, off);
                p2 += __shfl_xor_sync(FULLMASK, p2, off);
                p3 += __shfl_xor_sync(FULLMASK, p3, off);
            }
            if (lane == 0) {
                int i = base + r;
                xe[i * FOUT + 0] = p0 + sb2o[0];
                xe[i * FOUT + 1] = p1 + sb2o[1];
                xe[i * FOUT + 2] = p2 + sb2o[2];
                xe[i * FOUT + 3] = p3 + sb2o[3];
            }
        }
    }
}

// ---------------------------------------------------------------------------
extern "C" void kernel_launch(void* const* d_in, const int* in_sizes, int n_in,
                              void* d_out, int out_size) {
    const float* x     = (const float*)d_in[0];
    const float* W_se1 = (const float*)d_in[3];
    const float* b_se1 = (const float*)d_in[4];
    const float* W_se2 = (const float*)d_in[5];
    const float* b_se2 = (const float*)d_in[6];
    const float* W_g1a = (const float*)d_in[7];
    const float* b_g1a = (const float*)d_in[8];
    const float* W_g1b = (const float*)d_in[9];
    const float* b_g1b = (const float*)d_in[10];
    const float* W_g2a = (const float*)d_in[11];
    const float* b_g2a = (const float*)d_in[12];
    const float* W_g2b = (const float*)d_in[13];
    const float* b_g2b = (const float*)d_in[14];
    const float* W_oe1 = (const float*)d_in[15];
    const float* b_oe1 = (const float*)d_in[16];
    const float* W_oe2 = (const float*)d_in[17];
    const float* b_oe2 = (const float*)d_in[18];

    float* out    = (float*)d_out;
    float* out_h  = out;
    float* out_xe = out + XE_OFF;
    float* out_ei = out + EI_OFF;

    void *p_h0, *p_h1, *p_nbr;
    cudaGetSymbolAddress(&p_h0, g_h0);
    cudaGetSymbolAddress(&p_h1, g_h1);
    cudaGetSymbolAddress(&p_nbr, g_nbr);
    float* h0 = (float*)p_h0;
    float* h1 = (float*)p_h1;
    int*   nb = (int*)p_nbr;

    static const size_t gin_smem_base =
        (LATD * HIDD + HIDD * LATD + HIDD + LATD) * sizeof(float);
    static const size_t gin_smem_oe = gin_smem_base +
        (LATD * LATD + LATD + LATD * FOUT + FOUT) * sizeof(float);
    cudaFuncSetAttribute(k_gin<false>, cudaFuncAttributeMaxDynamicSharedMemorySize,
                         (int)gin_smem_base);
    cudaFuncSetAttribute(k_gin<true>, cudaFuncAttributeMaxDynamicSharedMemorySize,
                         (int)gin_smem_oe);

    // 1) space_emb -> h0
    k_space_emb<<<NN / 64, 256>>>(x, W_se1, b_se1, W_se2, b_se2, h0);
    // 2) kNN on h0[:, :3] -> nbr, ei written to output
    k_knn<<<GEV * 4, 128>>>(h0, nb, out_ei);
    // 3) GIN layer 1: h0 -> h1
    k_gin<false><<<NN / 32, 256, gin_smem_base>>>(h0, h1, nb,
        W_g1a, b_g1a, W_g1b, b_g1b, nullptr, nullptr, nullptr, nullptr, nullptr);
    // 4) GIN layer 2 + fused out_emb: h1 -> d_out (h), x_emb -> d_out
    k_gin<true><<<NN / 32, 256, gin_smem_oe>>>(h1, out_h, nb,
        W_g2a, b_g2a, W_g2b, b_g2b, W_oe1, b_oe1, W_oe2, b_oe2, out_xe);
}

// round 6
// speedup vs baseline: 1.9716x; 1.0970x over previous
#include <cuda_runtime.h>
#include <cuda_bf16.h>
#include <stdint.h>

// Problem constants
#define NN      8192
#define GEV     32
#define PER     256      // nodes per event
#define KK      15
#define FIN     4
#define FOUT    4
#define LATD    64
#define HIDD    128

#define H_ELEMS   (NN * LATD)          // 524288
#define XE_ELEMS  (NN * FOUT)          // 32768
#define NKE       (NN * KK)            // 122880
#define XE_OFF    (H_ELEMS)
#define EI_OFF    (H_ELEMS + XE_ELEMS) // 557056

#define FULLMASK 0xffffffffu

// Device scratch (no allocations allowed)
__device__ float g_h0[NN * LATD];
__device__ float g_h1[NN * LATD];
__device__ int   g_nbr[NN * KK];

// ---------------------------------------------------------------------------
// Kernel 1: space_emb FFN  h = leaky(x@W1+b1)@W2+b2
// 4 threads per row, each owns 16 output columns. grid 128 x 256.
// ---------------------------------------------------------------------------
__global__ void k_space_emb(const float* __restrict__ x,
                            const float* __restrict__ W1, const float* __restrict__ b1,
                            const float* __restrict__ W2, const float* __restrict__ b2,
                            float* __restrict__ hout) {
    __shared__ float sW1[FIN * LATD];
    __shared__ float sb1[LATD];
    __shared__ float sW2[LATD * LATD];
    __shared__ float sb2[LATD];
    int tid = threadIdx.x;
    for (int i = tid; i < FIN * LATD; i += blockDim.x) sW1[i] = W1[i];
    for (int i = tid; i < LATD; i += blockDim.x) { sb1[i] = b1[i]; sb2[i] = b2[i]; }
    {
        float4* sW24 = (float4*)sW2;
        const float4* W24 = (const float4*)W2;
#pragma unroll
        for (int i = 0; i < (LATD * LATD) / 4 / 256; ++i)
            sW24[tid + i * 256] = W24[tid + i * 256];
    }
    __syncthreads();

    int row = blockIdx.x * 64 + (tid >> 2);
    int q   = tid & 3;
    int c0  = q * 16;

    float xi0 = x[row * FIN + 0];
    float xi1 = x[row * FIN + 1];
    float xi2 = x[row * FIN + 2];
    float xi3 = x[row * FIN + 3];

    float acc[16];
#pragma unroll
    for (int c = 0; c < 16; ++c) acc[c] = sb2[c0 + c];

#pragma unroll 4
    for (int j = 0; j < LATD; ++j) {
        float tj = sb1[j]
                 + xi0 * sW1[0 * LATD + j]
                 + xi1 * sW1[1 * LATD + j]
                 + xi2 * sW1[2 * LATD + j]
                 + xi3 * sW1[3 * LATD + j];
        tj = (tj > 0.0f) ? tj : 0.01f * tj;
        const float* w2r = &sW2[j * LATD + c0];
#pragma unroll
        for (int c = 0; c < 16; ++c) acc[c] += tj * w2r[c];
    }
    float* o = &hout[row * LATD + c0];
#pragma unroll
    for (int c = 0; c < 16; ++c) o[c] = acc[c];
}

// ---------------------------------------------------------------------------
// Kernel 2: event-local kNN (k=15) on h[:, :3].
// 4 blocks per event, 64 queries per block, 256 threads: 4 threads per query
// (candidate stride 4), each keeps a sorted top-15 (uint8 local indices);
// two lexicographic (d, idx) merge rounds — matches lax.top_k tie-breaking.
// ---------------------------------------------------------------------------
__global__ void __launch_bounds__(256, 1)
k_knn(const float* __restrict__ h,
      int* __restrict__ nbr,
      float* __restrict__ out_ei) {
    __shared__ float   px[PER], py[PER], pz[PER];
    __shared__ float   mdA[256][KK];
    __shared__ uint8_t miA[256][KK];
    __shared__ float   mdB[128][KK];
    __shared__ uint8_t miB[128][KK];

    int tid  = threadIdx.x;           // 0..255
    int ev   = blockIdx.x >> 2;
    int quad = blockIdx.x & 3;
    int base = ev * PER;

    {
        int n = tid;
        px[n] = h[(base + n) * LATD + 0];
        py[n] = h[(base + n) * LATD + 1];
        pz[n] = h[(base + n) * LATD + 2];
    }
    __syncthreads();

    int lq  = quad * 64 + (tid >> 2);  // local query index in event
    int sub = tid & 3;                 // candidate residue

    float bd[KK];
    int   bi[KK];
#pragma unroll
    for (int s = 0; s < KK; ++s) { bd[s] = 3.0e38f; bi[s] = 0; }

    float xi = px[lq], yi = py[lq], zi = pz[lq];

    for (int j = sub; j < PER; j += 4) {
        float dx = __fadd_rn(xi, -px[j]);
        float dy = __fadd_rn(yi, -py[j]);
        float dz = __fadd_rn(zi, -pz[j]);
        float d  = __fadd_rn(__fadd_rn(__fmul_rn(dx, dx), __fmul_rn(dy, dy)),
                             __fmul_rn(dz, dz));
        if (j == lq) d = 3.3e38f;            // exclude self
        if (d < bd[KK - 1]) {
#pragma unroll
            for (int p = KK - 1; p >= 0; --p) {
                bool shift = (p > 0) && (d < bd[p - 1]);
                bool place = !shift && (d < bd[p]);
                if (shift)      { bd[p] = bd[p - 1]; bi[p] = bi[p - 1]; }
                else if (place) { bd[p] = d;         bi[p] = j;         }
            }
        }
    }
#pragma unroll
    for (int s = 0; s < KK; ++s) { mdA[tid][s] = bd[s]; miA[tid][s] = (uint8_t)bi[s]; }
    __syncthreads();

    // merge round 1: 128 threads, pairwise (sub 0,1) and (sub 2,3)
    if (tid < 128) {
        int q    = tid >> 1;
        int half = tid & 1;
        int ra = q * 4 + 2 * half, rb = ra + 1;
        int a = 0, b = 0;
#pragma unroll
        for (int s = 0; s < KK; ++s) {
            float da = mdA[ra][a], db = mdA[rb][b];
            int   ia = miA[ra][a], ib = miA[rb][b];
            bool takeA = (da < db) || (da == db && ia < ib);
            if (takeA) { mdB[tid][s] = da; miB[tid][s] = (uint8_t)ia; ++a; }
            else       { mdB[tid][s] = db; miB[tid][s] = (uint8_t)ib; ++b; }
        }
    }
    __syncthreads();

    // merge round 2: 64 threads, final output
    if (tid < 64) {
        int gid = base + quad * 64 + tid;
        float fgid = (float)gid;
        int ra = 2 * tid, rb = 2 * tid + 1;
        int a = 0, b = 0;
#pragma unroll
        for (int s = 0; s < KK; ++s) {
            float da = mdB[ra][a], db = mdB[rb][b];
            int   ia = miB[ra][a], ib = miB[rb][b];
            bool takeA = (da < db) || (da == db && ia < ib);
            int  pick  = takeA ? ia : ib;
            if (takeA) ++a; else ++b;
            int gj = base + pick;
            int e  = gid * KK + s;
            nbr[e] = gj;
            out_ei[e]       = (float)gj;
            out_ei[NKE + e] = fgid;
        }
    }
}

// ---------------------------------------------------------------------------
// Kernel 3: GIN layer as block-level SGEMM. 256 threads, 64 rows/block,
// grid 128. No shuffles: activations staged in smem (mT transposed for
// phase B; t padded row-major for phase C), weights row-major in smem.
// Phase B thread tile 4x8, phase C 4x4. FUSE_OE epilogue reuses mT/st
// buffers for h/u of the out_emb FFN.
// ---------------------------------------------------------------------------
#define MT_S 68    // mT / sh row stride
#define ST_S 132   // st / su row stride

template <bool FUSE_OE>
__global__ void __launch_bounds__(256, 1)
k_gin(const float* __restrict__ h_in,
      float* __restrict__ h_out,
      const int* __restrict__ nbr,
      const float* __restrict__ Wa, const float* __restrict__ ba,
      const float* __restrict__ Wb, const float* __restrict__ bb,
      const float* __restrict__ W1o, const float* __restrict__ b1o,
      const float* __restrict__ W2o, const float* __restrict__ b2o,
      float* __restrict__ xe) {
    extern __shared__ float sm[];
    float* sWa  = sm;                    // 64*128 = 8192
    float* sWb  = sWa + 8192;            // 128*64 = 8192
    float* sba  = sWb + 8192;            // 128
    float* sbb  = sba + 128;             // 64
    float* mT   = sbb + 64;              // 64*MT_S = 4352  (also sh for OE)
    float* st   = mT + 64 * MT_S;        // 64*ST_S = 8448  (also su for OE)
    float* sW1o = st + 64 * ST_S;        // 4096 (FUSE_OE)
    float* sW2o = sW1o + 4096;           // 256
    float* sb1o = sW2o + 256;            // 64
    float* sb2o = sb1o + 64;             // 4

    int tid = threadIdx.x;
    // ---- stage weights (row-major, vectorized) -----------------------------
    {
        const float4* Wa4 = (const float4*)Wa;
        const float4* Wb4 = (const float4*)Wb;
        float4* dA = (float4*)sWa;
        float4* dB = (float4*)sWb;
#pragma unroll
        for (int i = 0; i < 8; ++i) {
            dA[tid + i * 256] = Wa4[tid + i * 256];
            dB[tid + i * 256] = Wb4[tid + i * 256];
        }
        if (tid < 128) sba[tid] = ba[tid];
        if (tid < 64)  sbb[tid] = bb[tid];
        if (FUSE_OE) {
            const float4* W1o4 = (const float4*)W1o;
            float4* d3 = (float4*)sW1o;
#pragma unroll
            for (int i = 0; i < 4; ++i) d3[tid + i * 256] = W1o4[tid + i * 256];
            sW2o[tid] = W2o[tid];        // 256 floats exactly
            if (tid < 64) sb1o[tid] = b1o[tid];
            if (tid < 4)  sb2o[tid] = b2o[tid];
        }
    }

    int base = blockIdx.x * 64;

    // ---- Gather: m = h_i + sum of 15 neighbors -> mT[k][row] ---------------
    {
        int r  = tid >> 2;               // 0..63
        int qq = tid & 3;                // 16-col quarter
        int i  = base + r;
        const float4* h4 = (const float4*)h_in;
        const int* nb = &nbr[i * KK];
        float4 a0 = h4[i * 16 + qq * 4 + 0];
        float4 a1 = h4[i * 16 + qq * 4 + 1];
        float4 a2 = h4[i * 16 + qq * 4 + 2];
        float4 a3 = h4[i * 16 + qq * 4 + 3];
#pragma unroll
        for (int s = 0; s < KK; ++s) {
            int j = nb[s];
            float4 v0 = h4[j * 16 + qq * 4 + 0];
            float4 v1 = h4[j * 16 + qq * 4 + 1];
            float4 v2 = h4[j * 16 + qq * 4 + 2];
            float4 v3 = h4[j * 16 + qq * 4 + 3];
            a0.x += v0.x; a0.y += v0.y; a0.z += v0.z; a0.w += v0.w;
            a1.x += v1.x; a1.y += v1.y; a1.z += v1.z; a1.w += v1.w;
            a2.x += v2.x; a2.y += v2.y; a2.z += v2.z; a2.w += v2.w;
            a3.x += v3.x; a3.y += v3.y; a3.z += v3.z; a3.w += v3.w;
        }
        int k0 = qq * 16;
        float v[16] = {a0.x, a0.y, a0.z, a0.w, a1.x, a1.y, a1.z, a1.w,
                       a2.x, a2.y, a2.z, a2.w, a3.x, a3.y, a3.z, a3.w};
#pragma unroll
        for (int e = 0; e < 16; ++e) mT[(k0 + e) * MT_S + r] = v[e];
    }
    __syncthreads();

    int tx = tid & 15, ty = tid >> 4;
    int r0 = ty * 4;

    // ---- Phase B: t = relu(mT^T @ Wa + ba), thread tile 4x8 ----------------
    {
        int c0 = tx * 8;
        float acc[4][8];
#pragma unroll
        for (int i = 0; i < 4; ++i)
#pragma unroll
            for (int c = 0; c < 8; ++c) acc[i][c] = sba[c0 + c];

#pragma unroll 8
        for (int k = 0; k < 64; ++k) {
            float4 a  = *(const float4*)&mT[k * MT_S + r0];
            float4 b0 = *(const float4*)&sWa[k * HIDD + c0];
            float4 b1 = *(const float4*)&sWa[k * HIDD + c0 + 4];
            float av[4] = {a.x, a.y, a.z, a.w};
            float bv[8] = {b0.x, b0.y, b0.z, b0.w, b1.x, b1.y, b1.z, b1.w};
#pragma unroll
            for (int i = 0; i < 4; ++i)
#pragma unroll
                for (int c = 0; c < 8; ++c) acc[i][c] += av[i] * bv[c];
        }
#pragma unroll
        for (int i = 0; i < 4; ++i) {
            float4 q0, q1;
            q0.x = fmaxf(acc[i][0], 0.f); q0.y = fmaxf(acc[i][1], 0.f);
            q0.z = fmaxf(acc[i][2], 0.f); q0.w = fmaxf(acc[i][3], 0.f);
            q1.x = fmaxf(acc[i][4], 0.f); q1.y = fmaxf(acc[i][5], 0.f);
            q1.z = fmaxf(acc[i][6], 0.f); q1.w = fmaxf(acc[i][7], 0.f);
            *(float4*)&st[(r0 + i) * ST_S + c0]     = q0;
            *(float4*)&st[(r0 + i) * ST_S + c0 + 4] = q1;
        }
    }
    __syncthreads();

    // ---- Phase C: h_out = h_in + t @ Wb + bb, thread tile 4x4 --------------
    int c1 = tx * 4;
    float acc2[4][4];
#pragma unroll
    for (int i = 0; i < 4; ++i)
#pragma unroll
        for (int c = 0; c < 4; ++c) acc2[i][c] = sbb[c1 + c];

#pragma unroll 4
    for (int k2 = 0; k2 < HIDD; k2 += 4) {
        float4 ar[4], bk[4];
#pragma unroll
        for (int i = 0; i < 4; ++i) ar[i] = *(const float4*)&st[(r0 + i) * ST_S + k2];
#pragma unroll
        for (int j = 0; j < 4; ++j) bk[j] = *(const float4*)&sWb[(k2 + j) * LATD + c1];
#pragma unroll
        for (int i = 0; i < 4; ++i) {
            float aj[4] = {ar[i].x, ar[i].y, ar[i].z, ar[i].w};
#pragma unroll
            for (int j = 0; j < 4; ++j) {
                acc2[i][0] += aj[j] * bk[j].x;
                acc2[i][1] += aj[j] * bk[j].y;
                acc2[i][2] += aj[j] * bk[j].z;
                acc2[i][3] += aj[j] * bk[j].w;
            }
        }
    }
#pragma unroll
    for (int i = 0; i < 4; ++i) {
        float4 hv = *(const float4*)&h_in[(base + r0 + i) * LATD + c1];
        float4 o;
        o.x = hv.x + acc2[i][0];
        o.y = hv.y + acc2[i][1];
        o.z = hv.z + acc2[i][2];
        o.w = hv.w + acc2[i][3];
        *(float4*)&h_out[(base + r0 + i) * LATD + c1] = o;
        if (FUSE_OE) *(float4*)&mT[(r0 + i) * MT_S + c1] = o;   // sh = mT reuse
    }

    if (FUSE_OE) {
        __syncthreads();
        // ---- OE1: u = leaky(h @ W1o + b1o), thread tile 4x4 (sh=mT, su=st) -
        float u[4][4];
#pragma unroll
        for (int i = 0; i < 4; ++i)
#pragma unroll
            for (int c = 0; c < 4; ++c) u[i][c] = sb1o[c1 + c];
#pragma unroll 4
        for (int k = 0; k < LATD; k += 4) {
            float4 ar[4], bk[4];
#pragma unroll
            for (int i = 0; i < 4; ++i) ar[i] = *(const float4*)&mT[(r0 + i) * MT_S + k];
#pragma unroll
            for (int j = 0; j < 4; ++j) bk[j] = *(const float4*)&sW1o[(k + j) * LATD + c1];
#pragma unroll
            for (int i = 0; i < 4; ++i) {
                float aj[4] = {ar[i].x, ar[i].y, ar[i].z, ar[i].w};
#pragma unroll
                for (int j = 0; j < 4; ++j) {
                    u[i][0] += aj[j] * bk[j].x;
                    u[i][1] += aj[j] * bk[j].y;
                    u[i][2] += aj[j] * bk[j].z;
                    u[i][3] += aj[j] * bk[j].w;
                }
            }
        }
#pragma unroll
        for (int i = 0; i < 4; ++i) {
            float4 q;
            q.x = (u[i][0] > 0.f) ? u[i][0] : 0.01f * u[i][0];
            q.y = (u[i][1] > 0.f) ? u[i][1] : 0.01f * u[i][1];
            q.z = (u[i][2] > 0.f) ? u[i][2] : 0.01f * u[i][2];
            q.w = (u[i][3] > 0.f) ? u[i][3] : 0.01f * u[i][3];
            *(float4*)&st[(r0 + i) * ST_S + c1] = q;   // su = st reuse
        }
        __syncthreads();
        // ---- OE2: x_emb = u @ W2o + b2o; thread = (row, out-feature) -------
        {
            int row = tid >> 2;
            int oc  = tid & 3;
            float a = sb2o[oc];
#pragma unroll 8
            for (int k = 0; k < LATD; ++k)
                a += st[row * ST_S + k] * sW2o[k * FOUT + oc];
            xe[(base + row) * FOUT + oc] = a;
        }
    }
}

// ---------------------------------------------------------------------------
extern "C" void kernel_launch(void* const* d_in, const int* in_sizes, int n_in,
                              void* d_out, int out_size) {
    const float* x     = (const float*)d_in[0];
    const float* W_se1 = (const float*)d_in[3];
    const float* b_se1 = (const float*)d_in[4];
    const float* W_se2 = (const float*)d_in[5];
    const float* b_se2 = (const float*)d_in[6];
    const float* W_g1a = (const float*)d_in[7];
    const float* b_g1a = (const float*)d_in[8];
    const float* W_g1b = (const float*)d_in[9];
    const float* b_g1b = (const float*)d_in[10];
    const float* W_g2a = (const float*)d_in[11];
    const float* b_g2a = (const float*)d_in[12];
    const float* W_g2b = (const float*)d_in[13];
    const float* b_g2b = (const float*)d_in[14];
    const float* W_oe1 = (const float*)d_in[15];
    const float* b_oe1 = (const float*)d_in[16];
    const float* W_oe2 = (const float*)d_in[17];
    const float* b_oe2 = (const float*)d_in[18];

    float* out    = (float*)d_out;
    float* out_h  = out;
    float* out_xe = out + XE_OFF;
    float* out_ei = out + EI_OFF;

    void *p_h0, *p_h1, *p_nbr;
    cudaGetSymbolAddress(&p_h0, g_h0);
    cudaGetSymbolAddress(&p_h1, g_h1);
    cudaGetSymbolAddress(&p_nbr, g_nbr);
    float* h0 = (float*)p_h0;
    float* h1 = (float*)p_h1;
    int*   nb = (int*)p_nbr;

    static const size_t gin_smem_base =
        (size_t)(8192 + 8192 + 128 + 64 + 64 * MT_S + 64 * ST_S) * sizeof(float);
    static const size_t gin_smem_oe = gin_smem_base +
        (size_t)(4096 + 256 + 64 + 4) * sizeof(float);
    cudaFuncSetAttribute(k_gin<false>, cudaFuncAttributeMaxDynamicSharedMemorySize,
                         (int)gin_smem_base);
    cudaFuncSetAttribute(k_gin<true>, cudaFuncAttributeMaxDynamicSharedMemorySize,
                         (int)gin_smem_oe);

    // 1) space_emb -> h0
    k_space_emb<<<NN / 64, 256>>>(x, W_se1, b_se1, W_se2, b_se2, h0);
    // 2) kNN on h0[:, :3] -> nbr, ei written to output
    k_knn<<<GEV * 4, 256>>>(h0, nb, out_ei);
    // 3) GIN layer 1: h0 -> h1
    k_gin<false><<<NN / 64, 256, gin_smem_base>>>(h0, h1, nb,
        W_g1a, b_g1a, W_g1b, b_g1b, nullptr, nullptr, nullptr, nullptr, nullptr);
    // 4) GIN layer 2 + fused out_emb: h1 -> d_out (h), x_emb -> d_out
    k_gin<true><<<NN / 64, 256, gin_smem_oe>>>(h1, out_h, nb,
        W_g2a, b_g2a, W_g2b, b_g2b, W_oe1, b_oe1, W_oe2, b_oe2, out_xe);
}

// round 7
// speedup vs baseline: 2.0767x; 1.0533x over previous
#include <cuda_runtime.h>
#include <cuda_bf16.h>
#include <stdint.h>

// Problem constants
#define NN      8192
#define GEV     32
#define PER     256      // nodes per event
#define KK      15
#define FIN     4
#define FOUT    4
#define LATD    64
#define HIDD    128

#define H_ELEMS   (NN * LATD)          // 524288
#define XE_ELEMS  (NN * FOUT)          // 32768
#define NKE       (NN * KK)            // 122880
#define XE_OFF    (H_ELEMS)
#define EI_OFF    (H_ELEMS + XE_ELEMS) // 557056

#define FULLMASK 0xffffffffu

// Device scratch (no allocations allowed)
__device__ float g_h0[NN * LATD];
__device__ float g_h1[NN * LATD];
__device__ int   g_nbr[NN * KK];

// ---------------------------------------------------------------------------
// Kernel 1: space_emb FFN  h = leaky(x@W1+b1)@W2+b2
// 4 threads per row, each owns 16 output columns. grid 128 x 256.
// ---------------------------------------------------------------------------
__global__ void k_space_emb(const float* __restrict__ x,
                            const float* __restrict__ W1, const float* __restrict__ b1,
                            const float* __restrict__ W2, const float* __restrict__ b2,
                            float* __restrict__ hout) {
    __shared__ float sW1[FIN * LATD];
    __shared__ float sb1[LATD];
    __shared__ float sW2[LATD * LATD];
    __shared__ float sb2[LATD];
    int tid = threadIdx.x;
    for (int i = tid; i < FIN * LATD; i += blockDim.x) sW1[i] = W1[i];
    for (int i = tid; i < LATD; i += blockDim.x) { sb1[i] = b1[i]; sb2[i] = b2[i]; }
    {
        float4* sW24 = (float4*)sW2;
        const float4* W24 = (const float4*)W2;
#pragma unroll
        for (int i = 0; i < (LATD * LATD) / 4 / 256; ++i)
            sW24[tid + i * 256] = W24[tid + i * 256];
    }
    __syncthreads();

    int row = blockIdx.x * 64 + (tid >> 2);
    int q   = tid & 3;
    int c0  = q * 16;

    float xi0 = x[row * FIN + 0];
    float xi1 = x[row * FIN + 1];
    float xi2 = x[row * FIN + 2];
    float xi3 = x[row * FIN + 3];

    float acc[16];
#pragma unroll
    for (int c = 0; c < 16; ++c) acc[c] = sb2[c0 + c];

#pragma unroll 4
    for (int j = 0; j < LATD; ++j) {
        float tj = sb1[j]
                 + xi0 * sW1[0 * LATD + j]
                 + xi1 * sW1[1 * LATD + j]
                 + xi2 * sW1[2 * LATD + j]
                 + xi3 * sW1[3 * LATD + j];
        tj = (tj > 0.0f) ? tj : 0.01f * tj;
        const float* w2r = &sW2[j * LATD + c0];
#pragma unroll
        for (int c = 0; c < 16; ++c) acc[c] += tj * w2r[c];
    }
    float* o = &hout[row * LATD + c0];
#pragma unroll
    for (int c = 0; c < 16; ++c) o[c] = acc[c];
}

// ---------------------------------------------------------------------------
// Kernel 2: event-local kNN (k=15) on h[:, :3].
// 4 blocks per event, 64 queries per block, 256 threads: 4 threads per query
// (candidate stride 4), each keeps a sorted top-15 (uint8 local indices);
// two lexicographic (d, idx) merge rounds — matches lax.top_k tie-breaking.
// ---------------------------------------------------------------------------
__global__ void __launch_bounds__(256, 1)
k_knn(const float* __restrict__ h,
      int* __restrict__ nbr,
      float* __restrict__ out_ei) {
    __shared__ float   px[PER], py[PER], pz[PER];
    __shared__ float   mdA[256][KK];
    __shared__ uint8_t miA[256][KK];
    __shared__ float   mdB[128][KK];
    __shared__ uint8_t miB[128][KK];

    int tid  = threadIdx.x;           // 0..255
    int ev   = blockIdx.x >> 2;
    int quad = blockIdx.x & 3;
    int base = ev * PER;

    {
        int n = tid;
        px[n] = h[(base + n) * LATD + 0];
        py[n] = h[(base + n) * LATD + 1];
        pz[n] = h[(base + n) * LATD + 2];
    }
    __syncthreads();

    int lq  = quad * 64 + (tid >> 2);  // local query index in event
    int sub = tid & 3;                 // candidate residue

    float bd[KK];
    int   bi[KK];
#pragma unroll
    for (int s = 0; s < KK; ++s) { bd[s] = 3.0e38f; bi[s] = 0; }

    float xi = px[lq], yi = py[lq], zi = pz[lq];

    for (int j = sub; j < PER; j += 4) {
        float dx = __fadd_rn(xi, -px[j]);
        float dy = __fadd_rn(yi, -py[j]);
        float dz = __fadd_rn(zi, -pz[j]);
        float d  = __fadd_rn(__fadd_rn(__fmul_rn(dx, dx), __fmul_rn(dy, dy)),
                             __fmul_rn(dz, dz));
        if (j == lq) d = 3.3e38f;            // exclude self
        if (d < bd[KK - 1]) {
#pragma unroll
            for (int p = KK - 1; p >= 0; --p) {
                bool shift = (p > 0) && (d < bd[p - 1]);
                bool place = !shift && (d < bd[p]);
                if (shift)      { bd[p] = bd[p - 1]; bi[p] = bi[p - 1]; }
                else if (place) { bd[p] = d;         bi[p] = j;         }
            }
        }
    }
#pragma unroll
    for (int s = 0; s < KK; ++s) { mdA[tid][s] = bd[s]; miA[tid][s] = (uint8_t)bi[s]; }
    __syncthreads();

    // merge round 1: 128 threads, pairwise (sub 0,1) and (sub 2,3)
    if (tid < 128) {
        int q    = tid >> 1;
        int half = tid & 1;
        int ra = q * 4 + 2 * half, rb = ra + 1;
        int a = 0, b = 0;
#pragma unroll
        for (int s = 0; s < KK; ++s) {
            float da = mdA[ra][a], db = mdA[rb][b];
            int   ia = miA[ra][a], ib = miA[rb][b];
            bool takeA = (da < db) || (da == db && ia < ib);
            if (takeA) { mdB[tid][s] = da; miB[tid][s] = (uint8_t)ia; ++a; }
            else       { mdB[tid][s] = db; miB[tid][s] = (uint8_t)ib; ++b; }
        }
    }
    __syncthreads();

    // merge round 2: 64 threads, final output
    if (tid < 64) {
        int gid = base + quad * 64 + tid;
        float fgid = (float)gid;
        int ra = 2 * tid, rb = 2 * tid + 1;
        int a = 0, b = 0;
#pragma unroll
        for (int s = 0; s < KK; ++s) {
            float da = mdB[ra][a], db = mdB[rb][b];
            int   ia = miB[ra][a], ib = miB[rb][b];
            bool takeA = (da < db) || (da == db && ia < ib);
            int  pick  = takeA ? ia : ib;
            if (takeA) ++a; else ++b;
            int gj = base + pick;
            int e  = gid * KK + s;
            nbr[e] = gj;
            out_ei[e]       = (float)gj;
            out_ei[NKE + e] = fgid;
        }
    }
}

// ---------------------------------------------------------------------------
// Kernel 3: GIN layer as block-level SGEMM, slim tiles for occupancy 2.
// 256 threads, 32 rows/block, grid 256. Phase B 4x4 tile (a is a warp
// broadcast from transposed mT), phase C / OE 4x2 tiles. No shuffles.
// FUSE_OE epilogue reuses mT (as sh) and st (as su).
// ---------------------------------------------------------------------------
#define MT_S 36    // mT row stride (k-major, 32 rows + pad)
#define ST_S 132   // st row stride (128 + pad)
#define SH_S 68    // sh row stride (64 + pad), aliased onto mT

template <bool FUSE_OE>
__global__ void __launch_bounds__(256, 2)
k_gin(const float* __restrict__ h_in,
      float* __restrict__ h_out,
      const int* __restrict__ nbr,
      const float* __restrict__ Wa, const float* __restrict__ ba,
      const float* __restrict__ Wb, const float* __restrict__ bb,
      const float* __restrict__ W1o, const float* __restrict__ b1o,
      const float* __restrict__ W2o, const float* __restrict__ b2o,
      float* __restrict__ xe) {
    extern __shared__ float sm[];
    float* sWa  = sm;                    // 8192
    float* sWb  = sWa + 8192;            // 8192
    float* sba  = sWb + 8192;            // 128
    float* sbb  = sba + 128;             // 64
    float* mT   = sbb + 64;              // 64*MT_S = 2304 (reused as sh 32*SH_S=2176)
    float* st   = mT + 64 * MT_S;        // 32*ST_S = 4224 (reused as su)
    float* sW1o = st + 32 * ST_S;        // 4096 (FUSE_OE)
    float* sW2o = sW1o + 4096;           // 256
    float* sb1o = sW2o + 256;            // 64
    float* sb2o = sb1o + 64;             // 4

    int tid = threadIdx.x;
    // ---- stage weights (row-major, vectorized) -----------------------------
    {
        const float4* Wa4 = (const float4*)Wa;
        const float4* Wb4 = (const float4*)Wb;
        float4* dA = (float4*)sWa;
        float4* dB = (float4*)sWb;
#pragma unroll
        for (int i = 0; i < 8; ++i) {
            dA[tid + i * 256] = Wa4[tid + i * 256];
            dB[tid + i * 256] = Wb4[tid + i * 256];
        }
        if (tid < 128) sba[tid] = ba[tid];
        if (tid < 64)  sbb[tid] = bb[tid];
        if (FUSE_OE) {
            const float4* W1o4 = (const float4*)W1o;
            float4* d3 = (float4*)sW1o;
#pragma unroll
            for (int i = 0; i < 4; ++i) d3[tid + i * 256] = W1o4[tid + i * 256];
            sW2o[tid] = W2o[tid];        // 256 floats exactly
            if (tid < 64) sb1o[tid] = b1o[tid];
            if (tid < 4)  sb2o[tid] = b2o[tid];
        }
    }

    int base = blockIdx.x * 32;

    // ---- Gather: m = h_i + sum of 15 neighbors -> mT[k][row] ---------------
    // 8 threads per row; thread owns cols oct*8 .. oct*8+7 (2 float4).
    {
        int r   = tid >> 3;              // 0..31
        int oct = tid & 7;
        int i   = base + r;
        const float4* h4 = (const float4*)h_in;
        const int* nb = &nbr[i * KK];
        float4 a0 = h4[i * 16 + oct * 2];
        float4 a1 = h4[i * 16 + oct * 2 + 1];
#pragma unroll
        for (int s = 0; s < KK; ++s) {
            int j = nb[s];
            float4 v0 = h4[j * 16 + oct * 2];
            float4 v1 = h4[j * 16 + oct * 2 + 1];
            a0.x += v0.x; a0.y += v0.y; a0.z += v0.z; a0.w += v0.w;
            a1.x += v1.x; a1.y += v1.y; a1.z += v1.z; a1.w += v1.w;
        }
        int k0 = oct * 8;
        mT[(k0 + 0) * MT_S + r] = a0.x;
        mT[(k0 + 1) * MT_S + r] = a0.y;
        mT[(k0 + 2) * MT_S + r] = a0.z;
        mT[(k0 + 3) * MT_S + r] = a0.w;
        mT[(k0 + 4) * MT_S + r] = a1.x;
        mT[(k0 + 5) * MT_S + r] = a1.y;
        mT[(k0 + 6) * MT_S + r] = a1.z;
        mT[(k0 + 7) * MT_S + r] = a1.w;
    }
    __syncthreads();

    int r0 = (tid >> 5) * 4;            // warp-uniform row base (0..28)
    int cx = tid & 31;

    // ---- Phase B: t = relu(m @ Wa + ba), thread tile 4x4 -------------------
    {
        int c0 = cx * 4;
        float acc[4][4];
#pragma unroll
        for (int i = 0; i < 4; ++i)
#pragma unroll
            for (int c = 0; c < 4; ++c) acc[i][c] = sba[c0 + c];

#pragma unroll 8
        for (int k = 0; k < 64; ++k) {
            float4 a = *(const float4*)&mT[k * MT_S + r0];     // warp broadcast
            float4 b = *(const float4*)&sWa[k * HIDD + c0];
            acc[0][0] += a.x * b.x; acc[0][1] += a.x * b.y;
            acc[0][2] += a.x * b.z; acc[0][3] += a.x * b.w;
            acc[1][0] += a.y * b.x; acc[1][1] += a.y * b.y;
            acc[1][2] += a.y * b.z; acc[1][3] += a.y * b.w;
            acc[2][0] += a.z * b.x; acc[2][1] += a.z * b.y;
            acc[2][2] += a.z * b.z; acc[2][3] += a.z * b.w;
            acc[3][0] += a.w * b.x; acc[3][1] += a.w * b.y;
            acc[3][2] += a.w * b.z; acc[3][3] += a.w * b.w;
        }
#pragma unroll
        for (int i = 0; i < 4; ++i) {
            float4 q;
            q.x = fmaxf(acc[i][0], 0.f);
            q.y = fmaxf(acc[i][1], 0.f);
            q.z = fmaxf(acc[i][2], 0.f);
            q.w = fmaxf(acc[i][3], 0.f);
            *(float4*)&st[(r0 + i) * ST_S + c0] = q;
        }
    }
    __syncthreads();

    // ---- Phase C: h_out = h_in + t @ Wb + bb, thread tile 4x2 --------------
    int c1 = cx * 2;
    {
        float acc2[4][2];
#pragma unroll
        for (int i = 0; i < 4; ++i) { acc2[i][0] = sbb[c1]; acc2[i][1] = sbb[c1 + 1]; }

#pragma unroll 4
        for (int k2 = 0; k2 < HIDD; k2 += 4) {
            float4 ar[4];
            float2 bk[4];
#pragma unroll
            for (int i = 0; i < 4; ++i) ar[i] = *(const float4*)&st[(r0 + i) * ST_S + k2];
#pragma unroll
            for (int j = 0; j < 4; ++j) bk[j] = *(const float2*)&sWb[(k2 + j) * LATD + c1];
#pragma unroll
            for (int i = 0; i < 4; ++i) {
                acc2[i][0] += ar[i].x * bk[0].x + ar[i].y * bk[1].x
                            + ar[i].z * bk[2].x + ar[i].w * bk[3].x;
                acc2[i][1] += ar[i].x * bk[0].y + ar[i].y * bk[1].y
                            + ar[i].z * bk[2].y + ar[i].w * bk[3].y;
            }
        }
#pragma unroll
        for (int i = 0; i < 4; ++i) {
            float2 hv = *(const float2*)&h_in[(base + r0 + i) * LATD + c1];
            float2 o;
            o.x = hv.x + acc2[i][0];
            o.y = hv.y + acc2[i][1];
            *(float2*)&h_out[(base + r0 + i) * LATD + c1] = o;
            if (FUSE_OE) *(float2*)&mT[(r0 + i) * SH_S + c1] = o;  // sh = mT reuse
        }
    }

    if (FUSE_OE) {
        __syncthreads();
        // ---- OE1: u = leaky(h @ W1o + b1o), thread tile 4x2 (sh=mT) --------
        float u[4][2];
#pragma unroll
        for (int i = 0; i < 4; ++i) { u[i][0] = sb1o[c1]; u[i][1] = sb1o[c1 + 1]; }
#pragma unroll 4
        for (int k = 0; k < LATD; k += 4) {
            float4 ar[4];
            float2 bk[4];
#pragma unroll
            for (int i = 0; i < 4; ++i) ar[i] = *(const float4*)&mT[(r0 + i) * SH_S + k];
#pragma unroll
            for (int j = 0; j < 4; ++j) bk[j] = *(const float2*)&sW1o[(k + j) * LATD + c1];
#pragma unroll
            for (int i = 0; i < 4; ++i) {
                u[i][0] += ar[i].x * bk[0].x + ar[i].y * bk[1].x
                         + ar[i].z * bk[2].x + ar[i].w * bk[3].x;
                u[i][1] += ar[i].x * bk[0].y + ar[i].y * bk[1].y
                         + ar[i].z * bk[2].y + ar[i].w * bk[3].y;
            }
        }
#pragma unroll
        for (int i = 0; i < 4; ++i) {
            float2 q;
            q.x = (u[i][0] > 0.f) ? u[i][0] : 0.01f * u[i][0];
            q.y = (u[i][1] > 0.f) ? u[i][1] : 0.01f * u[i][1];
            *(float2*)&st[(r0 + i) * ST_S + c1] = q;   // su = st reuse
        }
        __syncthreads();
        // ---- OE2: x_emb = u @ W2o + b2o; 128 threads = (row, feature) ------
        if (tid < 128) {
            int row = tid >> 2;
            int oc  = tid & 3;
            float a = sb2o[oc];
#pragma unroll 8
            for (int k = 0; k < LATD; ++k)
                a += st[row * ST_S + k] * sW2o[k * FOUT + oc];
            xe[(base + row) * FOUT + oc] = a;
        }
    }
}

// ---------------------------------------------------------------------------
extern "C" void kernel_launch(void* const* d_in, const int* in_sizes, int n_in,
                              void* d_out, int out_size) {
    const float* x     = (const float*)d_in[0];
    const float* W_se1 = (const float*)d_in[3];
    const float* b_se1 = (const float*)d_in[4];
    const float* W_se2 = (const float*)d_in[5];
    const float* b_se2 = (const float*)d_in[6];
    const float* W_g1a = (const float*)d_in[7];
    const float* b_g1a = (const float*)d_in[8];
    const float* W_g1b = (const float*)d_in[9];
    const float* b_g1b = (const float*)d_in[10];
    const float* W_g2a = (const float*)d_in[11];
    const float* b_g2a = (const float*)d_in[12];
    const float* W_g2b = (const float*)d_in[13];
    const float* b_g2b = (const float*)d_in[14];
    const float* W_oe1 = (const float*)d_in[15];
    const float* b_oe1 = (const float*)d_in[16];
    const float* W_oe2 = (const float*)d_in[17];
    const float* b_oe2 = (const float*)d_in[18];

    float* out    = (float*)d_out;
    float* out_h  = out;
    float* out_xe = out + XE_OFF;
    float* out_ei = out + EI_OFF;

    void *p_h0, *p_h1, *p_nbr;
    cudaGetSymbolAddress(&p_h0, g_h0);
    cudaGetSymbolAddress(&p_h1, g_h1);
    cudaGetSymbolAddress(&p_nbr, g_nbr);
    float* h0 = (float*)p_h0;
    float* h1 = (float*)p_h1;
    int*   nb = (int*)p_nbr;

    static const size_t gin_smem_base =
        (size_t)(8192 + 8192 + 128 + 64 + 64 * MT_S + 32 * ST_S) * sizeof(float);
    static const size_t gin_smem_oe = gin_smem_base +
        (size_t)(4096 + 256 + 64 + 4) * sizeof(float);
    cudaFuncSetAttribute(k_gin<false>, cudaFuncAttributeMaxDynamicSharedMemorySize,
                         (int)gin_smem_base);
    cudaFuncSetAttribute(k_gin<true>, cudaFuncAttributeMaxDynamicSharedMemorySize,
                         (int)gin_smem_oe);

    // 1) space_emb -> h0
    k_space_emb<<<NN / 64, 256>>>(x, W_se1, b_se1, W_se2, b_se2, h0);
    // 2) kNN on h0[:, :3] -> nbr, ei written to output
    k_knn<<<GEV * 4, 256>>>(h0, nb, out_ei);
    // 3) GIN layer 1: h0 -> h1
    k_gin<false><<<NN / 32, 256, gin_smem_base>>>(h0, h1, nb,
        W_g1a, b_g1a, W_g1b, b_g1b, nullptr, nullptr, nullptr, nullptr, nullptr);
    // 4) GIN layer 2 + fused out_emb: h1 -> d_out (h), x_emb -> d_out
    k_gin<true><<<NN / 32, 256, gin_smem_oe>>>(h1, out_h, nb,
        W_g2a, b_g2a, W_g2b, b_g2b, W_oe1, b_oe1, W_oe2, b_oe2, out_xe);
}